// round 14
// baseline (speedup 1.0000x reference)
#include <cuda_runtime.h>
#include <math.h>

// GATLayer: h[100000,128] f32, W[64,128] f32, src[E] i32, dst[E] i32 -> out[100000,64] f32
//
// Pipeline (CSR-first, fused scoring+softmax+aggregation):
//   K0 init:    deg = 0
//   K1 gemm:    z = h @ W^T            (register-tiled SGEMM — round-9 proven)
//   K2 count:   deg[dst]++             (coalesced, int atomics)
//   K3 scan:    exclusive scan deg -> off  (warp-shuffle scan)
//   K4 scatter: src ids into CSR order by dst
//   K5 fused:   per-node: dot(z[src],z[dst]) per edge + softmax + weighted
//               sum + ELU, src rows register-cached for deg <= 24

#define NODES_CAP 100000
#define EDGES_CAP 1600000
#define IN_DIM 128
#define OUT_DIM 64
#define SCAN_BLK 256
#define MAX_BLKS 512   // ceil(100000/256)=391 <= 512
#define REG_E 24       // register-cached rows; P(deg<=24 | Poisson(16)) ~ 0.983

__device__ float g_z[(size_t)NODES_CAP * OUT_DIM];   // 25.6 MB (L2-resident)
__device__ int   g_ecsr[EDGES_CAP];                  // CSR-ordered src ids
__device__ int   g_deg[NODES_CAP];                   // counts, then scatter cursor
__device__ int   g_off[NODES_CAP + 1];               // CSR offsets
__device__ int   g_bsum[MAX_BLKS];                   // scan partials

// ---------------------------------------------------------------------------
__global__ void init_kernel(int n_nodes) {
    int i = blockIdx.x * blockDim.x + threadIdx.x;
    if (i < n_nodes) g_deg[i] = 0;
}

// ---------------------------------------------------------------------------
// SGEMM: z[n][o] = sum_k h[n][k] * W[o][k]
// Block tile 128x64, 256 threads, 4x8 micro-tile. W fully staged in SMEM.
// (measured correct + perf-adequate in round 9)
__global__ __launch_bounds__(256) void gemm_kernel(
    const float* __restrict__ h, const float* __restrict__ W, int n_nodes)
{
    __shared__ float ws[IN_DIM][OUT_DIM];   // [k][o]
    __shared__ float hs[16][132];           // [k][node], padded

    int tid = threadIdx.x;

    for (int i = tid; i < OUT_DIM * IN_DIM / 4; i += 256) {
        int o  = i >> 5;
        int k4 = (i & 31) << 2;
        float4 w4 = ((const float4*)W)[i];
        ws[k4 + 0][o] = w4.x;
        ws[k4 + 1][o] = w4.y;
        ws[k4 + 2][o] = w4.z;
        ws[k4 + 3][o] = w4.w;
    }

    int nr = tid >> 3;
    int oc = tid & 7;
    int node_base = blockIdx.x * 128;

    float acc[4][8];
#pragma unroll
    for (int i = 0; i < 4; i++)
#pragma unroll
        for (int j = 0; j < 8; j++) acc[i][j] = 0.f;

    for (int kc = 0; kc < IN_DIM; kc += 16) {
        __syncthreads();
#pragma unroll
        for (int i = tid; i < 512; i += 256) {
            int n = i >> 2;
            int q = i & 3;
            int gn = node_base + n;
            float4 v = make_float4(0.f, 0.f, 0.f, 0.f);
            if (gn < n_nodes)
                v = *(const float4*)(h + (size_t)gn * IN_DIM + kc + (q << 2));
            hs[(q << 2) + 0][n] = v.x;
            hs[(q << 2) + 1][n] = v.y;
            hs[(q << 2) + 2][n] = v.z;
            hs[(q << 2) + 3][n] = v.w;
        }
        __syncthreads();
#pragma unroll
        for (int k = 0; k < 16; k++) {
            float4 a  = *(const float4*)&hs[k][nr << 2];
            float4 b0 = *(const float4*)&ws[kc + k][oc << 3];
            float4 b1 = *(const float4*)&ws[kc + k][(oc << 3) + 4];
            float av[4] = {a.x, a.y, a.z, a.w};
            float bv[8] = {b0.x, b0.y, b0.z, b0.w, b1.x, b1.y, b1.z, b1.w};
#pragma unroll
            for (int i = 0; i < 4; i++)
#pragma unroll
                for (int j = 0; j < 8; j++)
                    acc[i][j] += av[i] * bv[j];
        }
    }

#pragma unroll
    for (int i = 0; i < 4; i++) {
        int gn = node_base + (nr << 2) + i;
        if (gn < n_nodes) {
            float4 r0 = make_float4(acc[i][0], acc[i][1], acc[i][2], acc[i][3]);
            float4 r1 = make_float4(acc[i][4], acc[i][5], acc[i][6], acc[i][7]);
            *(float4*)(g_z + (size_t)gn * OUT_DIM + (oc << 3))     = r0;
            *(float4*)(g_z + (size_t)gn * OUT_DIM + (oc << 3) + 4) = r1;
        }
    }
}

// ---------------------------------------------------------------------------
// deg[dst]++ — coalesced read, spread int atomics.
__global__ __launch_bounds__(256) void count_kernel(
    const int* __restrict__ dst, int n_edges)
{
    int i = blockIdx.x * blockDim.x + threadIdx.x;
    if (i < n_edges) atomicAdd(&g_deg[dst[i]], 1);
}

// ---------------------------------------------------------------------------
// Exclusive scan of g_deg into g_off (3 kernels; warp-shuffle block scan).
__global__ __launch_bounds__(SCAN_BLK) void scan_part_kernel(int n) {
    __shared__ int wsum[SCAN_BLK / 32];
    int tid  = threadIdx.x;
    int lane = tid & 31;
    int wid  = tid >> 5;
    int i = blockIdx.x * SCAN_BLK + tid;
    int v = (i < n) ? g_deg[i] : 0;

    int incl = v;
#pragma unroll
    for (int o = 1; o < 32; o <<= 1) {
        int t = __shfl_up_sync(0xffffffffu, incl, o);
        if (lane >= o) incl += t;
    }
    if (lane == 31) wsum[wid] = incl;
    __syncthreads();
    if (wid == 0) {
        int wv = (lane < SCAN_BLK / 32) ? wsum[lane] : 0;
        int wi = wv;
#pragma unroll
        for (int o = 1; o < 32; o <<= 1) {
            int t = __shfl_up_sync(0xffffffffu, wi, o);
            if (lane >= o) wi += t;
        }
        if (lane < SCAN_BLK / 32) wsum[lane] = wi - wv;  // exclusive
    }
    __syncthreads();
    int excl = incl - v + wsum[wid];
    if (i < n) g_off[i] = excl;
    if (tid == SCAN_BLK - 1) g_bsum[blockIdx.x] = excl + v;  // block total
}

__global__ __launch_bounds__(MAX_BLKS) void scan_top_kernel(int nblocks) {
    __shared__ int sm[MAX_BLKS];
    int tid = threadIdx.x;
    int v = (tid < nblocks) ? g_bsum[tid] : 0;
    sm[tid] = v;
    __syncthreads();
#pragma unroll
    for (int o = 1; o < MAX_BLKS; o <<= 1) {
        int t = (tid >= o) ? sm[tid - o] : 0;
        __syncthreads();
        sm[tid] += t;
        __syncthreads();
    }
    if (tid < nblocks) g_bsum[tid] = sm[tid] - v;  // exclusive
}

__global__ __launch_bounds__(SCAN_BLK) void scan_add_kernel(int n, int n_edges) {
    int i = blockIdx.x * SCAN_BLK + threadIdx.x;
    if (i < n) {
        g_off[i] += g_bsum[blockIdx.x];
        g_deg[i] = 0;                           // reset -> scatter cursor
    }
    if (i == 0) g_off[n] = n_edges;
}

// ---------------------------------------------------------------------------
// Scatter src ids into CSR order by dst. One random 4B write per edge.
__global__ __launch_bounds__(256) void scatter_kernel(
    const int* __restrict__ src, const int* __restrict__ dst, int n_edges)
{
    int i = blockIdx.x * blockDim.x + threadIdx.x;
    if (i >= n_edges) return;
    int d = dst[i];
    int pos = atomicAdd(&g_deg[d], 1);
    g_ecsr[g_off[d] + pos] = src[i];
}

// ---------------------------------------------------------------------------
__device__ __forceinline__ float warp_sum(float x) {
#pragma unroll
    for (int o = 16; o; o >>= 1)
        x += __shfl_xor_sync(0xffffffffu, x, o);
    return x;
}

// One warp per node. Warp holds z[dst] row (float2/lane). Each z[src] row is
// gathered ONCE: serves the attention dot (warp reduce) AND the weighted
// accumulation (rows register-cached for deg <= REG_E; online-softmax 2-pass
// fallback beyond).
__global__ __launch_bounds__(128) void fused_kernel(
    float* __restrict__ out, int n_nodes)
{
    int node = (blockIdx.x * blockDim.x + threadIdx.x) >> 5;
    int lane = threadIdx.x & 31;
    if (node >= n_nodes) return;

    const float2* zp = (const float2*)g_z;
    float2* op = (float2*)out;

    int off = g_off[node];
    int end = g_off[node + 1];
    int cnt = end - off;

    if (cnt == 0) {                         // isolated node: agg row = 0, elu(0)=0
        op[(size_t)node * 32 + lane] = make_float2(0.f, 0.f);
        return;
    }

    float2 d = zp[(size_t)node * 32 + lane];   // dst row, register-resident
    float ax = 0.f, ay = 0.f;

    if (cnt <= REG_E) {
        // ---- register path (~98% of nodes) ----
        int sn = (lane < cnt) ? g_ecsr[off + lane] : 0;

        float2 rows[REG_E];
#pragma unroll
        for (int j = 0; j < REG_E; j++) {
            int sj = __shfl_sync(0xffffffffu, sn, j);
            rows[j] = (j < cnt) ? zp[(size_t)sj * 32 + lane] : make_float2(0.f, 0.f);
        }

        float evs[REG_E];
#pragma unroll
        for (int j = 0; j < REG_E; j++) {
            float dp = warp_sum(rows[j].x * d.x + rows[j].y * d.y);
            evs[j] = (j < cnt) ? (dp > 0.f ? dp : 0.2f * dp) : -INFINITY;
        }

        float m = -INFINITY;
#pragma unroll
        for (int j = 0; j < REG_E; j++) m = fmaxf(m, evs[j]);
        float s = 0.f;
#pragma unroll
        for (int j = 0; j < REG_E; j++) { evs[j] = __expf(evs[j] - m); s += evs[j]; }
        float inv = 1.f / s;
#pragma unroll
        for (int j = 0; j < REG_E; j++) {
            float w = evs[j] * inv;
            ax = fmaf(w, rows[j].x, ax);
            ay = fmaf(w, rows[j].y, ay);
        }
    } else {
        // ---- generic path: online softmax, two passes over src rows ----
        float m = -INFINITY, s = 0.f;
        for (int jj = off; jj < end; jj++) {
            int sj = g_ecsr[jj];
            float2 v = zp[(size_t)sj * 32 + lane];
            float dp = warp_sum(v.x * d.x + v.y * d.y);
            float ev = dp > 0.f ? dp : 0.2f * dp;
            float mn = fmaxf(m, ev);
            s = s * __expf(m - mn) + __expf(ev - mn);
            m = mn;
        }
        float inv = 1.f / s;
        for (int jj = off; jj < end; jj++) {
            int sj = g_ecsr[jj];
            float2 v = zp[(size_t)sj * 32 + lane];
            float dp = warp_sum(v.x * d.x + v.y * d.y);
            float ev = dp > 0.f ? dp : 0.2f * dp;
            float w = __expf(ev - m) * inv;
            ax = fmaf(w, v.x, ax);
            ay = fmaf(w, v.y, ay);
        }
    }

    float2 r;
    r.x = ax > 0.f ? ax : (__expf(ax) - 1.f);
    r.y = ay > 0.f ? ay : (__expf(ay) - 1.f);
    op[(size_t)node * 32 + lane] = r;
}

// ---------------------------------------------------------------------------
extern "C" void kernel_launch(void* const* d_in, const int* in_sizes, int n_in,
                              void* d_out, int out_size) {
    const float* h   = (const float*)d_in[0];
    const float* W   = (const float*)d_in[1];
    const int*   src = (const int*)d_in[2];
    const int*   dst = (const int*)d_in[3];
    float* out = (float*)d_out;

    int n_nodes = in_sizes[0] / IN_DIM;
    int n_edges = in_sizes[2];
    int nblocks = (n_nodes + SCAN_BLK - 1) / SCAN_BLK;

    init_kernel<<<nblocks, SCAN_BLK>>>(n_nodes);
    gemm_kernel<<<(n_nodes + 127) / 128, 256>>>(h, W, n_nodes);
    count_kernel<<<(n_edges + 255) / 256, 256>>>(dst, n_edges);
    scan_part_kernel<<<nblocks, SCAN_BLK>>>(n_nodes);
    scan_top_kernel<<<1, MAX_BLKS>>>(nblocks);
    scan_add_kernel<<<nblocks, SCAN_BLK>>>(n_nodes, n_edges);
    scatter_kernel<<<(n_edges + 255) / 256, 256>>>(src, dst, n_edges);
    fused_kernel<<<(n_nodes * 32 + 127) / 128, 128>>>(out, n_nodes);
}